// round 1
// baseline (speedup 1.0000x reference)
#include <cuda_runtime.h>
#include <cuda_bf16.h>

#define N_EDGES_CONST 4000000

__global__ __launch_bounds__(256) void bamboo_edge_kernel(
    const int* __restrict__ row,
    const int* __restrict__ col,
    const float* __restrict__ dij,
    const float* __restrict__ charge,
    const float* __restrict__ c6,
    const float* __restrict__ r0,
    float* __restrict__ out,
    int E)
{
    int i = blockIdx.x * blockDim.x + threadIdx.x;
    if (i >= E) return;

    // ---- constants ----
    const float ELE_FACTOR = 332.0637f;
    const float EWALD_F = 1.12837917f;
    const float EWALD_P = 0.3275911f;
    const float A0 = 0.254829592f, A1 = -0.284496736f, A2 = 1.421413741f,
                A3 = -1.453152027f, A4 = 1.061405429f;
    const float COUL_BETA = 18.7f;
    const float COUL_R0 = 2.2f;
    const float G_EWALD = 0.3f;
    const float DISP_C = 1.0f / 1000000.0f;      // 1 / 10^6
    const float R45_6 = 8303.765625f;            // 4.5^6

    int ri = row[i];
    int ci = col[i];

    float dx = dij[3 * i + 0];
    float dy = dij[3 * i + 1];
    float dz = dij[3 * i + 2];

    float r2 = dx * dx + dy * dy + dz * dz;
    float rinv = rsqrtf(r2);
    float rij = r2 * rinv;          // |d|
    float rinv2 = rinv * rinv;

    // ---- Coulomb ----
    float qi = __ldg(&charge[ri]);
    float qj = __ldg(&charge[ci]);
    float prefactor = ELE_FACTOR * qi * qj * rinv;

    float x = (COUL_BETA / COUL_R0) * (rij - COUL_R0);   // in [-10.2, 66.4]
    float ex = __expf(x);
    float damp = ex / (1.0f + ex);                        // sigmoid(x)
    float sp = __logf(1.0f + ex) * (1.0f / COUL_BETA);    // softplus(beta*z)/beta
    float s = rij * (1.0f / COUL_R0) / (1.0f + sp);

    float ecoul = prefactor * s;
    float fcoul = prefactor * damp * s * s;

    // Ewald short-range erfc correction
    float grij = G_EWALD * rij;
    float expm2 = __expf(-grij * grij);
    float t = 1.0f / (1.0f + EWALD_P * grij);
    float erfc = t * (A0 + t * (A1 + t * (A2 + t * (A3 + t * A4)))) * expm2;
    ecoul += prefactor * (erfc - 1.0f);
    fcoul += prefactor * (erfc + EWALD_F * grij * expm2 - 1.0f);

    float cf = fcoul * rinv2;

    // ---- Dispersion (D3-CSO) ----
    float c6i = __ldg(&c6[ri]);
    float c6j = __ldg(&c6[ci]);
    float r0i = __ldg(&r0[ri]);
    float r0j = __ldg(&r0[ci]);

    float c6ij = sqrtf(c6i * c6j);
    float r0ij = 0.5f * (r0i + r0j);

    float r4 = r2 * r2;
    float r5 = r4 * rij;
    float r6 = r4 * r2 + R45_6;
    float r6inv = 1.0f / r6;

    float e = __expf(rij - 2.5f * r0ij);
    float einv = 1.0f / (1.0f + e);
    float cso = 0.85f + 0.82f * einv;

    float edisp = -c6ij * r6inv * cso + c6ij * DISP_C;
    float fdisp = -6.0f * c6ij * r5 * r6inv * r6inv * cso
                  - c6ij * r6inv * (0.82f * e * einv * einv);
    float df = fdisp * rinv;

    // ---- outputs: [ecoul E][coul_fij 3E][edisp E][disp_fij 3E] ----
    float* ecoul_o = out;
    float* cfij_o  = out + (size_t)E;
    float* edisp_o = out + (size_t)4 * E;
    float* dfij_o  = out + (size_t)5 * E;

    ecoul_o[i] = ecoul;
    cfij_o[3 * i + 0] = dx * cf;
    cfij_o[3 * i + 1] = dy * cf;
    cfij_o[3 * i + 2] = dz * cf;
    edisp_o[i] = edisp;
    dfij_o[3 * i + 0] = dx * df;
    dfij_o[3 * i + 1] = dy * df;
    dfij_o[3 * i + 2] = dz * df;
}

extern "C" void kernel_launch(void* const* d_in, const int* in_sizes, int n_in,
                              void* d_out, int out_size)
{
    const int*   row    = (const int*)d_in[0];
    const int*   col    = (const int*)d_in[1];
    const float* dij    = (const float*)d_in[2];
    const float* charge = (const float*)d_in[3];
    const float* c6     = (const float*)d_in[4];
    const float* r0     = (const float*)d_in[5];
    float* out = (float*)d_out;

    int E = in_sizes[0];
    int threads = 256;
    int blocks = (E + threads - 1) / threads;
    bamboo_edge_kernel<<<blocks, threads>>>(row, col, dij, charge, c6, r0, out, E);
}

// round 2
// speedup vs baseline: 2.1406x; 2.1406x over previous
#include <cuda_runtime.h>
#include <cuda_bf16.h>

#define MAX_ATOMS 200000

// packed per-atom data: {charge*sqrt(ELE_FACTOR), sqrt(c6), 0.5*r0, unused}
__device__ float4 g_atom[MAX_ATOMS];

__global__ __launch_bounds__(256) void pack_atoms_kernel(
    const float* __restrict__ charge,
    const float* __restrict__ c6,
    const float* __restrict__ r0,
    int n)
{
    int i = blockIdx.x * blockDim.x + threadIdx.x;
    if (i >= n || i >= MAX_ATOMS) return;
    float4 v;
    v.x = charge[i] * 18.2226124f;   // sqrt(332.0637)
    v.y = sqrtf(c6[i]);
    v.z = 0.5f * r0[i];
    v.w = 0.0f;
    g_atom[i] = v;
}

__global__ __launch_bounds__(256) void bamboo_edge_kernel(
    const int* __restrict__ row,
    const int* __restrict__ col,
    const float* __restrict__ dij,
    float* __restrict__ out,
    int E)
{
    int i = blockIdx.x * blockDim.x + threadIdx.x;
    if (i >= E) return;

    // ---- constants ----
    const float EWALD_F = 1.12837917f;
    const float EWALD_P = 0.3275911f;
    const float A0 = 0.254829592f, A1 = -0.284496736f, A2 = 1.421413741f,
                A3 = -1.453152027f, A4 = 1.061405429f;
    const float COUL_BETA = 18.7f;
    const float COUL_R0 = 2.2f;
    const float G_EWALD = 0.3f;
    const float DISP_C = 1.0f / 1000000.0f;      // 1 / 10^6
    const float R45_6 = 8303.765625f;            // 4.5^6

    int ri = row[i];
    int ci = col[i];

    float dx = dij[3 * i + 0];
    float dy = dij[3 * i + 1];
    float dz = dij[3 * i + 2];

    // two wide random gathers instead of six scalar ones
    float4 ai = g_atom[ri];
    float4 aj = g_atom[ci];

    float r2 = dx * dx + dy * dy + dz * dz;
    float rinv = rsqrtf(r2);
    float rij = r2 * rinv;          // |d|
    float rinv2 = rinv * rinv;

    // ---- Coulomb ----
    float prefactor = ai.x * aj.x * rinv;   // ELE_FACTOR folded into packed charges

    float x = (COUL_BETA / COUL_R0) * (rij - COUL_R0);   // in [-10.2, 66.4]
    float ex = __expf(x);
    float damp = ex / (1.0f + ex);                        // sigmoid(x)
    float sp = __logf(1.0f + ex) * (1.0f / COUL_BETA);    // softplus(beta*z)/beta
    float s = rij * (1.0f / COUL_R0) / (1.0f + sp);

    float ecoul = prefactor * s;
    float fcoul = prefactor * damp * s * s;

    // Ewald short-range erfc correction
    float grij = G_EWALD * rij;
    float expm2 = __expf(-grij * grij);
    float t = 1.0f / (1.0f + EWALD_P * grij);
    float erfc = t * (A0 + t * (A1 + t * (A2 + t * (A3 + t * A4)))) * expm2;
    ecoul += prefactor * (erfc - 1.0f);
    fcoul += prefactor * (erfc + EWALD_F * grij * expm2 - 1.0f);

    float cf = fcoul * rinv2;

    // ---- Dispersion (D3-CSO) ----
    float c6ij = ai.y * aj.y;       // sqrt(c6i)*sqrt(c6j)
    float r0ij = ai.z + aj.z;       // 0.5*(r0i + r0j)

    float r4 = r2 * r2;
    float r5 = r4 * rij;
    float r6 = r4 * r2 + R45_6;
    float r6inv = 1.0f / r6;

    float e = __expf(rij - 2.5f * r0ij);
    float einv = 1.0f / (1.0f + e);
    float cso = 0.85f + 0.82f * einv;

    float edisp = -c6ij * r6inv * cso + c6ij * DISP_C;
    float fdisp = -6.0f * c6ij * r5 * r6inv * r6inv * cso
                  - c6ij * r6inv * (0.82f * e * einv * einv);
    float df = fdisp * rinv;

    // ---- outputs: [ecoul E][coul_fij 3E][edisp E][disp_fij 3E] ----
    float* ecoul_o = out;
    float* cfij_o  = out + (size_t)E;
    float* edisp_o = out + (size_t)4 * E;
    float* dfij_o  = out + (size_t)5 * E;

    ecoul_o[i] = ecoul;
    cfij_o[3 * i + 0] = dx * cf;
    cfij_o[3 * i + 1] = dy * cf;
    cfij_o[3 * i + 2] = dz * cf;
    edisp_o[i] = edisp;
    dfij_o[3 * i + 0] = dx * df;
    dfij_o[3 * i + 1] = dy * df;
    dfij_o[3 * i + 2] = dz * df;
}

extern "C" void kernel_launch(void* const* d_in, const int* in_sizes, int n_in,
                              void* d_out, int out_size)
{
    const int*   row    = (const int*)d_in[0];
    const int*   col    = (const int*)d_in[1];
    const float* dij    = (const float*)d_in[2];
    const float* charge = (const float*)d_in[3];
    const float* c6     = (const float*)d_in[4];
    const float* r0     = (const float*)d_in[5];
    float* out = (float*)d_out;

    int E = in_sizes[0];
    int n_atoms = in_sizes[3];

    int threads = 256;
    pack_atoms_kernel<<<(n_atoms + threads - 1) / threads, threads>>>(charge, c6, r0, n_atoms);
    bamboo_edge_kernel<<<(E + threads - 1) / threads, threads>>>(row, col, dij, out, E);
}